// round 2
// baseline (speedup 1.0000x reference)
#include <cuda_runtime.h>
#include <math.h>

// Problem constants
#define NB   256   // batch
#define NL   256   // sequence length (== LB)
#define NC   32    // channels
#define NS   32    // states
#define NROWS (NB*NL)
#define C_LOG2PI 58.812066125099048f   // 32 * log(2*pi)

#define FULLMASK 0xffffffffu
typedef unsigned long long ull;

// ---------------- packed f32x2 helpers ----------------
__device__ __forceinline__ ull pack2(float a, float b) {
    ull r; asm("mov.b64 %0, {%1, %2};" : "=l"(r) : "f"(a), "f"(b)); return r;
}
__device__ __forceinline__ float2 unpack2(ull v) {
    float2 r; asm("mov.b64 {%0, %1}, %2;" : "=f"(r.x), "=f"(r.y) : "l"(v)); return r;
}
__device__ __forceinline__ ull fma2(ull a, ull b, ull c) {
    ull d; asm("fma.rn.f32x2 %0, %1, %2, %3;" : "=l"(d) : "l"(a), "l"(b), "l"(c)); return d;
}
__device__ __forceinline__ ull add2(ull a, ull b) {
    ull d; asm("add.rn.f32x2 %0, %1, %2;" : "=l"(d) : "l"(a), "l"(b)); return d;
}

// ---------------- device scratch (allocation-free) ----------------
__device__ ull   g_Linv2[NS * 528];      // triangular-packed Linv, duplicated into float2
__device__ ull   g_dmu2[2 * 16 * 32];    // per-half incremental mean deltas, duplicated
__device__ float g_ld[NS];               // logdet per state
__device__ float g_log_trans[NS * NS];   // log(softmax(T)+1e-8)
__device__ float g_log_init[NS];         // log softmax of initial distribution
__device__ int   g_rowargmax[NS];        // argmax of each transition row
__device__ float g_emlp[NROWS * NS];     // emission log probs, [b*L+t][s]

// =====================================================================
// Kernel 0: per-state prep (blocks 0..31) + transition/init/dmu prep (block 32)
// One warp per block.
// =====================================================================
__global__ void prep_kernel(const float* __restrict__ cc,      // covar_chol (S,C,C)
                            const float* __restrict__ means,   // (S,C)
                            const float* __restrict__ tm,      // transition (S,S)
                            const float* __restrict__ idist) { // (S,)
    const int lane = threadIdx.x;
    const int s = blockIdx.x;

    if (s < NS) {
        __shared__ float T[32][33];
        __shared__ float A[32][33];
        __shared__ float LI[32][33];

        // Load T = tril(cc[s]) with exp on diagonal
        for (int i = 0; i < 32; i++) {
            float v = cc[s * 1024 + i * 32 + lane];
            if (lane > i) v = 0.0f;
            else if (lane == i) v = expf(v);
            T[i][lane] = v;
        }
        __syncwarp();

        // covar = T T^t + 1e-6 I
        for (int i = 0; i < 32; i++) {
            float acc = (lane == i) ? 1e-6f : 0.0f;
            #pragma unroll
            for (int k = 0; k < 32; k++) acc += T[i][k] * T[lane][k];
            A[i][lane] = acc;
        }
        __syncwarp();

        // In-place Cholesky (lower) of A
        for (int k = 0; k < 32; k++) {
            float d = sqrtf(A[k][k]);
            __syncwarp();
            if (lane == k) A[k][k] = d;
            if (lane > k)  A[lane][k] = A[lane][k] / d;
            __syncwarp();
            if (lane > k) {
                float lik = A[lane][k];
                for (int j = k + 1; j <= lane; j++) A[lane][j] -= lik * A[j][k];
            }
            __syncwarp();
        }

        // Triangular inverse: lane owns column `lane` of LI
        for (int i = 0; i < 32; i++) {
            float val = 0.0f;
            if (i >= lane) {
                float ss = (i == lane) ? 1.0f : 0.0f;
                for (int k = lane; k < i; k++) ss -= A[i][k] * LI[k][lane];
                val = ss / A[i][i];
            }
            LI[i][lane] = val;
        }
        __syncwarp();

        // logdet = 2 * sum(log(diag))
        float dl = logf(A[lane][lane]);
        #pragma unroll
        for (int o = 16; o; o >>= 1) dl += __shfl_xor_sync(FULLMASK, dl, o);
        if (lane == 0) g_ld[s] = 2.0f * dl;

        // triangular-packed duplicated Linv
        for (int idx = lane; idx < 528; idx += 32) {
            int i = (int)((sqrtf(8.0f * (float)idx + 1.0f) - 1.0f) * 0.5f);
            while ((i + 1) * (i + 2) / 2 <= idx) i++;
            while (i * (i + 1) / 2 > idx) i--;
            int j = idx - i * (i + 1) / 2;
            float v = LI[i][j];
            g_Linv2[s * 528 + idx] = pack2(v, v);
        }
    } else {
        // ---- block 32: log-softmax of init, log(softmax+1e-8) of transition,
        //      row argmax, incremental-mu tables
        float v = idist[lane];
        float mx = v;
        #pragma unroll
        for (int o = 16; o; o >>= 1) mx = fmaxf(mx, __shfl_xor_sync(FULLMASK, mx, o));
        float e = expf(v - mx);
        float sm = e;
        #pragma unroll
        for (int o = 16; o; o >>= 1) sm += __shfl_xor_sync(FULLMASK, sm, o);
        g_log_init[lane] = (v - mx) - logf(sm);

        for (int i = 0; i < 32; i++) {
            float tv = tm[i * 32 + lane];
            float m2 = tv;
            #pragma unroll
            for (int o = 16; o; o >>= 1) m2 = fmaxf(m2, __shfl_xor_sync(FULLMASK, m2, o));
            float ee = expf(tv - m2);
            float ssum = ee;
            #pragma unroll
            for (int o = 16; o; o >>= 1) ssum += __shfl_xor_sync(FULLMASK, ssum, o);
            g_log_trans[i * 32 + lane] = logf(ee / ssum + 1e-8f);

            // first-occurrence argmax of the row (softmax is monotone)
            float bv = tv; int bi = lane;
            #pragma unroll
            for (int o = 16; o; o >>= 1) {
                float ov = __shfl_xor_sync(FULLMASK, bv, o);
                int   oi = __shfl_xor_sync(FULLMASK, bi, o);
                if (ov > bv || (ov == bv && oi < bi)) { bv = ov; bi = oi; }
            }
            if (lane == 0) g_rowargmax[i] = bi;
        }

        // dmu tables: per half h, state-step k:
        //   k==0: -mu[h*16]       k>0: mu[h*16+k-1] - mu[h*16+k]
        for (int h = 0; h < 2; h++) {
            for (int k = 0; k < 16; k++) {
                int s0 = h * 16 + k;
                float dv = (k == 0) ? (-means[s0 * 32 + lane])
                                    : (means[(s0 - 1) * 32 + lane] - means[s0 * 32 + lane]);
                g_dmu2[(h * 16 + k) * 32 + lane] = pack2(dv, dv);
            }
        }
    }
}

// =====================================================================
// Kernel 1: emission log probs.
// 2 rows per thread via packed f32x2; states split 16 per block (blockIdx.y).
// Incremental mean diff (no xp registers -> no spills). Even/odd accumulator
// split halves the FFMA2 dependency chain.
// Block = 128 threads, grid = (256, 2). smem ~70KB -> 3 blocks/SM.
// =====================================================================
__global__ void __launch_bounds__(128) emlp_kernel(const float* __restrict__ em) {
    extern __shared__ ull sh[];
    ull*   sL  = sh;                  // 16*528 = 8448 entries
    ull*   sD  = sh + 8448;           // 16*32  = 512 entries
    float* sLd = (float*)(sh + 8960); // 16 floats

    const int h = blockIdx.y;
    const ull* gL = g_Linv2 + h * 8448;
    for (int i = threadIdx.x; i < 8448; i += 128) sL[i] = gL[i];
    const ull* gD = g_dmu2 + h * 512;
    for (int i = threadIdx.x; i < 512; i += 128) sD[i] = gD[i];
    if (threadIdx.x < 16) sLd[threadIdx.x] = g_ld[h * 16 + threadIdx.x];
    __syncthreads();

    const int row0 = (blockIdx.x * 128 + threadIdx.x) * 2;
    const float4* p = (const float4*)(em + (size_t)row0 * 32);

    ull xd[32];
    #pragma unroll
    for (int q = 0; q < 8; q++) {
        float4 f0 = p[q];
        float4 f1 = p[8 + q];
        xd[4*q+0] = pack2(f0.x, f1.x);
        xd[4*q+1] = pack2(f0.y, f1.y);
        xd[4*q+2] = pack2(f0.z, f1.z);
        xd[4*q+3] = pack2(f0.w, f1.w);
    }

    float* outp = g_emlp + (size_t)row0 * NS + h * 16;

    for (int k = 0; k < 16; k++) {
        const ull* dm = sD + k * 32;
        #pragma unroll
        for (int j = 0; j < 32; j++) xd[j] = add2(xd[j], dm[j]);   // xd = x - mu_k

        const ull* Ls = sL + k * 528;
        ull macc = 0ull;
        #pragma unroll
        for (int i = 0; i < 32; i++) {
            ull ae = 0ull, ao = 0ull;        // even/odd j chains (2x ILP)
            const int tri = i * (i + 1) / 2;
            #pragma unroll
            for (int j = 0; j <= i; j += 2) ae = fma2(Ls[tri + j], xd[j], ae);
            #pragma unroll
            for (int j = 1; j <= i; j += 2) ao = fma2(Ls[tri + j], xd[j], ao);
            ull a = add2(ae, ao);
            macc = fma2(a, a, macc);         // mahal += solved^2 (both rows)
        }
        float2 m = unpack2(macc);
        const float c = sLd[k] + C_LOG2PI;
        outp[k]      = -0.5f * (m.x + c);
        outp[NS + k] = -0.5f * (m.y + c);
    }
}

// =====================================================================
// Kernel 2: fused Viterbi + AR prediction. One block (256 thr) per batch.
// Warps 0..7 compute AR partials; warp 0 then runs the Viterbi recursion.
// =====================================================================
__global__ void __launch_bounds__(256) vp_kernel(const float* __restrict__ em,
                                                 const float* __restrict__ W,
                                                 const float* __restrict__ means,
                                                 float* __restrict__ out) {
    const int b    = blockIdx.x;
    const int lane = threadIdx.x & 31;
    const int g    = threadIdx.x >> 5;

    __shared__ float red[8][32];
    __shared__ int   s_state;

    // ---- AR partial sums (all 8 warps) ----
    const float* ebm = em + (size_t)b * NL * NC;
    float acc = 0.0f;
    #pragma unroll
    for (int l = 0; l < 32; l++) {
        const int ll = g * 32 + l;
        acc += ebm[ll * NC + lane] * W[ll * NC + lane];
    }
    red[g][lane] = acc;

    // ---- Viterbi (warp 0 only) ----
    if (g == 0) {
        float ltcol[32];
        #pragma unroll
        for (int i = 0; i < 32; i++) ltcol[i] = g_log_trans[i * 32 + lane];

        const float* eb = g_emlp + (size_t)b * NL * NS;
        float delta = g_log_init[lane] + eb[lane];

        #pragma unroll 4
        for (int t = 1; t < NL; t++) {
            const float emv = eb[t * NS + lane];
            float v[32];
            #pragma unroll
            for (int i = 0; i < 32; i++)
                v[i] = __shfl_sync(FULLMASK, delta, i) + ltcol[i];
            #pragma unroll
            for (int st = 16; st >= 1; st >>= 1) {
                #pragma unroll
                for (int i = 0; i < 16; i++)
                    if (i < st) v[i] = fmaxf(v[i], v[i + st]);
            }
            delta = v[0] + emv;
        }

        // first-occurrence argmax over lanes
        float bv = delta; int bi = lane;
        #pragma unroll
        for (int o = 16; o; o >>= 1) {
            float ov = __shfl_xor_sync(FULLMASK, bv, o);
            int   oi = __shfl_xor_sync(FULLMASK, bi, o);
            if (ov > bv || (ov == bv && oi < bi)) { bv = ov; bi = oi; }
        }
        if (lane == 0) s_state = g_rowargmax[bi];
    }
    __syncthreads();

    // ---- final combine (warp 0) ----
    if (g == 0) {
        float ssum = 0.0f;
        #pragma unroll
        for (int k = 0; k < 8; k++) ssum += red[k][lane];
        out[b * NC + lane] = ssum + means[s_state * NC + lane];
    }
}

// =====================================================================
extern "C" void kernel_launch(void* const* d_in, const int* in_sizes, int n_in,
                              void* d_out, int out_size) {
    const float* em    = (const float*)d_in[0];  // emissions (B,L,C)
    const float* tm    = (const float*)d_in[1];  // transition_matrix (S,S)
    const float* idist = (const float*)d_in[2];  // initial_distribution (S,)
    const float* means = (const float*)d_in[3];  // means (S,C)
    const float* cc    = (const float*)d_in[4];  // covar_chol (S,C,C)
    const float* W     = (const float*)d_in[5];  // W (LB,C,PW)
    float* out = (float*)d_out;

    prep_kernel<<<NS + 1, 32>>>(cc, means, tm, idist);

    const int shbytes = (8448 + 512) * (int)sizeof(ull) + 16 * (int)sizeof(float);
    cudaFuncSetAttribute(emlp_kernel, cudaFuncAttributeMaxDynamicSharedMemorySize, shbytes);
    emlp_kernel<<<dim3(256, 2), 128, shbytes>>>(em);

    vp_kernel<<<NB, 256>>>(em, W, means, out);
}

// round 3
// speedup vs baseline: 1.5633x; 1.5633x over previous
#include <cuda_runtime.h>
#include <math.h>

// Problem constants
#define NB   256   // batch
#define NL   256   // sequence length (== LB)
#define NC   32    // channels
#define NS   32    // states
#define NROWS (NB*NL)
#define C_LOG2PI 58.812066125099048f   // 32 * log(2*pi)
#define LROW 544   // padded triangular size per state (tri(i) + ceil(i/2) layout)

#define FULLMASK 0xffffffffu
typedef unsigned long long ull;

// ---------------- packed f32x2 helpers ----------------
__device__ __forceinline__ ull pack2(float a, float b) {
    ull r; asm("mov.b64 %0, {%1, %2};" : "=l"(r) : "f"(a), "f"(b)); return r;
}
__device__ __forceinline__ float2 unpack2(ull v) {
    float2 r; asm("mov.b64 {%0, %1}, %2;" : "=f"(r.x), "=f"(r.y) : "l"(v)); return r;
}
__device__ __forceinline__ ull fma2(ull a, ull b, ull c) {
    ull d; asm("fma.rn.f32x2 %0, %1, %2, %3;" : "=l"(d) : "l"(a), "l"(b), "l"(c)); return d;
}
__device__ __forceinline__ ull add2(ull a, ull b) {
    ull d; asm("add.rn.f32x2 %0, %1, %2;" : "=l"(d) : "l"(a), "l"(b)); return d;
}
// 16-byte vector shared load (LDS.128)
__device__ __forceinline__ ulonglong2 lds128(unsigned addr) {
    ulonglong2 v;
    asm("ld.shared.v2.u64 {%0, %1}, [%2];" : "=l"(v.x), "=l"(v.y) : "r"(addr));
    return v;
}

// ---------------- device scratch (allocation-free) ----------------
__device__ ull   g_Linv2[NS * LROW];     // padded-triangular Linv, duplicated float2 (pads = 0)
__device__ ull   g_dmu2[2 * 16 * 32];    // per-half incremental mean deltas, duplicated
__device__ float g_ld[NS];               // logdet per state
__device__ float g_log_trans[NS * NS];   // log(softmax(T)+1e-8)
__device__ float g_log_init[NS];         // log softmax of initial distribution
__device__ int   g_rowargmax[NS];        // argmax of each transition row
__device__ float g_emlp[NROWS * NS];     // emission log probs, [b*L+t][s]

// =====================================================================
// Kernel 0: per-state prep (blocks 0..31): register/shuffle Cholesky +
// triangular inverse. Block 32: transition/init/dmu prep.
// One warp per block.
// =====================================================================
__global__ void prep_kernel(const float* __restrict__ cc,      // covar_chol (S,C,C)
                            const float* __restrict__ means,   // (S,C)
                            const float* __restrict__ tm,      // transition (S,S)
                            const float* __restrict__ idist) { // (S,)
    const int lane = threadIdx.x;
    const int s = blockIdx.x;

    if (s < NS) {
        __shared__ float T[32][33];

        // Load T = tril(cc[s]) with exp on diagonal (coalesced: element (i,lane))
        #pragma unroll
        for (int i = 0; i < 32; i++) {
            float v = cc[s * 1024 + i * 32 + lane];
            if (lane > i) v = 0.0f;
            else if (lane == i) v = expf(v);
            T[i][lane] = v;
        }
        __syncwarp();

        // lane's row of T into registers
        float tr[32];
        #pragma unroll
        for (int k = 0; k < 32; k++) tr[k] = T[lane][k];

        // a[j] = covar[lane][j] = dot(row_lane, row_j) + eps on diag
        float a[32];
        #pragma unroll
        for (int j = 0; j < 32; j++) {
            float a0 = 0.0f, a1 = 0.0f;
            #pragma unroll
            for (int k = 0; k < 32; k += 2) {
                a0 += tr[k]     * T[j][k];       // broadcast LDS
                a1 += tr[k + 1] * T[j][k + 1];
            }
            a[j] = a0 + a1 + ((j == lane) ? 1e-6f : 0.0f);
        }

        // Register Cholesky: lane owns row `lane` (cols j<=lane valid)
        #pragma unroll
        for (int k = 0; k < 32; k++) {
            float dk = __shfl_sync(FULLMASK, a[k], k);
            float d = sqrtf(dk);
            if (lane == k)      a[k] = d;
            else if (lane > k)  a[k] = a[k] / d;
            #pragma unroll
            for (int j = k + 1; j < 32; j++) {
                float Ljk = __shfl_sync(FULLMASK, a[k], j);
                if (lane >= j) a[j] -= a[k] * Ljk;
            }
        }

        // logdet = 2 * sum(log(diag));  diag of L on lane i is a[i]
        float dl = logf(a[lane]);
        #pragma unroll
        for (int o = 16; o; o >>= 1) dl += __shfl_xor_sync(FULLMASK, dl, o);
        if (lane == 0) g_ld[s] = 2.0f * dl;

        // Forward substitution: lane owns column `lane` of Linv.
        // x[i] = (delta_{i,lane} - sum_{k<i} L[i][k]*x[k]) / L[i][i];  x[i]=0 for i<lane.
        float x[32];
        #pragma unroll
        for (int i = 0; i < 32; i++) {
            float ss = (lane == i) ? 1.0f : 0.0f;
            #pragma unroll
            for (int k = 0; k < 32; k++) {
                if (k < i) {
                    float Lik = __shfl_sync(FULLMASK, a[k], i);
                    ss -= Lik * x[k];
                }
            }
            float Lii = __shfl_sync(FULLMASK, a[i], i);
            x[i] = (lane <= i) ? (ss / Lii) : 0.0f;
        }

        // Store padded-triangular duplicated Linv. Row i starts at
        // R_i = tri(i) + ceil(i/2); even-i rows have a zero pad at R_i+i+1.
        #pragma unroll
        for (int i = 0; i < 32; i++) {
            const int Ri = i * (i + 1) / 2 + ((i + 1) >> 1);
            if (lane <= i)
                g_Linv2[s * LROW + Ri + lane] = pack2(x[i], x[i]);
            if (((i & 1) == 0) && lane == i + 1)
                g_Linv2[s * LROW + Ri + i + 1] = 0ull;
        }
    } else {
        // ---- block 32: log-softmax of init, log(softmax+1e-8) of transition,
        //      row argmax, incremental-mu tables
        float v = idist[lane];
        float mx = v;
        #pragma unroll
        for (int o = 16; o; o >>= 1) mx = fmaxf(mx, __shfl_xor_sync(FULLMASK, mx, o));
        float e = expf(v - mx);
        float sm = e;
        #pragma unroll
        for (int o = 16; o; o >>= 1) sm += __shfl_xor_sync(FULLMASK, sm, o);
        g_log_init[lane] = (v - mx) - logf(sm);

        for (int i = 0; i < 32; i++) {
            float tv = tm[i * 32 + lane];
            float m2 = tv;
            #pragma unroll
            for (int o = 16; o; o >>= 1) m2 = fmaxf(m2, __shfl_xor_sync(FULLMASK, m2, o));
            float ee = expf(tv - m2);
            float ssum = ee;
            #pragma unroll
            for (int o = 16; o; o >>= 1) ssum += __shfl_xor_sync(FULLMASK, ssum, o);
            g_log_trans[i * 32 + lane] = logf(ee / ssum + 1e-8f);

            // first-occurrence argmax of the row (softmax is monotone)
            float bv = tv; int bi = lane;
            #pragma unroll
            for (int o = 16; o; o >>= 1) {
                float ov = __shfl_xor_sync(FULLMASK, bv, o);
                int   oi = __shfl_xor_sync(FULLMASK, bi, o);
                if (ov > bv || (ov == bv && oi < bi)) { bv = ov; bi = oi; }
            }
            if (lane == 0) g_rowargmax[i] = bi;
        }

        // dmu tables: per half h, state-step k:
        //   k==0: -mu[h*16]     k>0: mu[h*16+k-1] - mu[h*16+k]
        for (int h = 0; h < 2; h++) {
            for (int k = 0; k < 16; k++) {
                int s0 = h * 16 + k;
                float dv = (k == 0) ? (-means[s0 * 32 + lane])
                                    : (means[(s0 - 1) * 32 + lane] - means[s0 * 32 + lane]);
                g_dmu2[(h * 16 + k) * 32 + lane] = pack2(dv, dv);
            }
        }
    }
}

// =====================================================================
// Kernel 1: emission log probs.
// 4 rows per thread (two f32x2 pairs); 16 states per block (blockIdx.y halves).
// L fetched via LDS.128 (2 elements), each load feeds 4 FFMA2 -> LDS amortized 4x.
// Block = 128 threads, grid = (128, 2), smem ~74KB, 2 blocks/SM.
// =====================================================================
__global__ void __launch_bounds__(128, 2) emlp_kernel(const float* __restrict__ em) {
    extern __shared__ ull sh[];
    // layout: [0, 8704) L (16 states * 544), [8704, 9216) dmu, then 16 floats logdet
    const int h = blockIdx.y;
    const ull* gL = g_Linv2 + h * 16 * LROW;
    for (int i = threadIdx.x; i < 16 * LROW; i += 128) sh[i] = gL[i];
    const ull* gD = g_dmu2 + h * 512;
    for (int i = threadIdx.x; i < 512; i += 128) sh[8704 + i] = gD[i];
    float* sLd = (float*)(sh + 9216);
    if (threadIdx.x < 16) sLd[threadIdx.x] = g_ld[h * 16 + threadIdx.x];
    __syncthreads();

    const unsigned sbase = (unsigned)__cvta_generic_to_shared(sh);
    const unsigned dbase = sbase + 8704u * 8u;

    const int row0 = (blockIdx.x * 128 + threadIdx.x) * 4;
    const float4* p = (const float4*)(em + (size_t)row0 * 32);

    ull xa[32], xb[32];   // pair A = rows 0,1 ; pair B = rows 2,3
    #pragma unroll
    for (int q = 0; q < 8; q++) {
        float4 f0 = p[q], f1 = p[8 + q], f2 = p[16 + q], f3 = p[24 + q];
        xa[4*q+0] = pack2(f0.x, f1.x); xa[4*q+1] = pack2(f0.y, f1.y);
        xa[4*q+2] = pack2(f0.z, f1.z); xa[4*q+3] = pack2(f0.w, f1.w);
        xb[4*q+0] = pack2(f2.x, f3.x); xb[4*q+1] = pack2(f2.y, f3.y);
        xb[4*q+2] = pack2(f2.z, f3.z); xb[4*q+3] = pack2(f2.w, f3.w);
    }

    float* outp = g_emlp + (size_t)row0 * NS + h * 16;

    for (int k = 0; k < 16; k++) {
        // xd += dmu_k  (both pairs; 16 LDS.128 serve 64 add2)
        const unsigned da = dbase + (unsigned)(k * 32 * 8);
        #pragma unroll
        for (int jp = 0; jp < 16; jp++) {
            ulonglong2 v = lds128(da + jp * 16);
            xa[2*jp]   = add2(xa[2*jp],   v.x);
            xa[2*jp+1] = add2(xa[2*jp+1], v.y);
            xb[2*jp]   = add2(xb[2*jp],   v.x);
            xb[2*jp+1] = add2(xb[2*jp+1], v.y);
        }

        const unsigned la = sbase + (unsigned)(k * LROW * 8);
        ull ma = 0ull, mb = 0ull;
        #pragma unroll
        for (int i = 0; i < 32; i++) {
            const int Ri = i * (i + 1) / 2 + ((i + 1) >> 1);
            const int np = (i + 2) >> 1;
            ull aA = 0ull, bA = 0ull, aB = 0ull, bB = 0ull;
            #pragma unroll
            for (int jp = 0; jp < np; jp++) {
                ulonglong2 v = lds128(la + (unsigned)((Ri + 2 * jp) * 8));
                aA = fma2(v.x, xa[2*jp],   aA);
                bA = fma2(v.y, xa[2*jp+1], bA);   // pad elems are 0 -> safe
                aB = fma2(v.x, xb[2*jp],   aB);
                bB = fma2(v.y, xb[2*jp+1], bB);
            }
            ull sA = add2(aA, bA);
            ull sB = add2(aB, bB);
            ma = fma2(sA, sA, ma);
            mb = fma2(sB, sB, mb);
        }
        float2 m0 = unpack2(ma), m1 = unpack2(mb);
        const float c = sLd[k] + C_LOG2PI;
        outp[k]          = -0.5f * (m0.x + c);
        outp[NS + k]     = -0.5f * (m0.y + c);
        outp[2 * NS + k] = -0.5f * (m1.x + c);
        outp[3 * NS + k] = -0.5f * (m1.y + c);
    }
}

// =====================================================================
// Kernel 2: fused Viterbi + AR prediction. One block (256 thr) per batch.
// =====================================================================
__global__ void __launch_bounds__(256) vp_kernel(const float* __restrict__ em,
                                                 const float* __restrict__ W,
                                                 const float* __restrict__ means,
                                                 float* __restrict__ out) {
    const int b    = blockIdx.x;
    const int lane = threadIdx.x & 31;
    const int g    = threadIdx.x >> 5;

    __shared__ float red[8][32];
    __shared__ int   s_state;

    // ---- AR partial sums (all 8 warps) ----
    const float* ebm = em + (size_t)b * NL * NC;
    float acc = 0.0f;
    #pragma unroll
    for (int l = 0; l < 32; l++) {
        const int ll = g * 32 + l;
        acc += ebm[ll * NC + lane] * W[ll * NC + lane];
    }
    red[g][lane] = acc;

    // ---- Viterbi (warp 0 only) ----
    if (g == 0) {
        float ltcol[32];
        #pragma unroll
        for (int i = 0; i < 32; i++) ltcol[i] = g_log_trans[i * 32 + lane];

        const float* eb = g_emlp + (size_t)b * NL * NS;
        float delta = g_log_init[lane] + eb[lane];

        #pragma unroll 4
        for (int t = 1; t < NL; t++) {
            const float emv = eb[t * NS + lane];
            float v[32];
            #pragma unroll
            for (int i = 0; i < 32; i++)
                v[i] = __shfl_sync(FULLMASK, delta, i) + ltcol[i];
            #pragma unroll
            for (int st = 16; st >= 1; st >>= 1) {
                #pragma unroll
                for (int i = 0; i < 16; i++)
                    if (i < st) v[i] = fmaxf(v[i], v[i + st]);
            }
            delta = v[0] + emv;
        }

        // first-occurrence argmax over lanes
        float bv = delta; int bi = lane;
        #pragma unroll
        for (int o = 16; o; o >>= 1) {
            float ov = __shfl_xor_sync(FULLMASK, bv, o);
            int   oi = __shfl_xor_sync(FULLMASK, bi, o);
            if (ov > bv || (ov == bv && oi < bi)) { bv = ov; bi = oi; }
        }
        if (lane == 0) s_state = g_rowargmax[bi];
    }
    __syncthreads();

    // ---- final combine (warp 0) ----
    if (g == 0) {
        float ssum = 0.0f;
        #pragma unroll
        for (int k = 0; k < 8; k++) ssum += red[k][lane];
        out[b * NC + lane] = ssum + means[s_state * NC + lane];
    }
}

// =====================================================================
extern "C" void kernel_launch(void* const* d_in, const int* in_sizes, int n_in,
                              void* d_out, int out_size) {
    const float* em    = (const float*)d_in[0];  // emissions (B,L,C)
    const float* tm    = (const float*)d_in[1];  // transition_matrix (S,S)
    const float* idist = (const float*)d_in[2];  // initial_distribution (S,)
    const float* means = (const float*)d_in[3];  // means (S,C)
    const float* cc    = (const float*)d_in[4];  // covar_chol (S,C,C)
    const float* W     = (const float*)d_in[5];  // W (LB,C,PW)
    float* out = (float*)d_out;

    prep_kernel<<<NS + 1, 32>>>(cc, means, tm, idist);

    const int shbytes = 9216 * (int)sizeof(ull) + 16 * (int)sizeof(float);
    cudaFuncSetAttribute(emlp_kernel, cudaFuncAttributeMaxDynamicSharedMemorySize, shbytes);
    emlp_kernel<<<dim3(128, 2), 128, shbytes>>>(em);

    vp_kernel<<<NB, 256>>>(em, W, means, out);
}

// round 4
// speedup vs baseline: 1.5903x; 1.0173x over previous
#include <cuda_runtime.h>
#include <math.h>

// Problem constants
#define NB   256   // batch
#define NL   256   // sequence length (== LB)
#define NC   32    // channels
#define NS   32    // states
#define NROWS (NB*NL)
#define C_LOG2PI 58.812066125099048f   // 32 * log(2*pi)
#define LROW 544   // padded triangular size per state (tri(i) + ceil(i/2) layout)

#define FULLMASK 0xffffffffu
typedef unsigned long long ull;

// ---------------- packed f32x2 helpers ----------------
__device__ __forceinline__ ull pack2(float a, float b) {
    ull r; asm("mov.b64 %0, {%1, %2};" : "=l"(r) : "f"(a), "f"(b)); return r;
}
__device__ __forceinline__ float2 unpack2(ull v) {
    float2 r; asm("mov.b64 {%0, %1}, %2;" : "=f"(r.x), "=f"(r.y) : "l"(v)); return r;
}
__device__ __forceinline__ ull fma2(ull a, ull b, ull c) {
    ull d; asm("fma.rn.f32x2 %0, %1, %2, %3;" : "=l"(d) : "l"(a), "l"(b), "l"(c)); return d;
}
__device__ __forceinline__ ull add2(ull a, ull b) {
    ull d; asm("add.rn.f32x2 %0, %1, %2;" : "=l"(d) : "l"(a), "l"(b)); return d;
}
// 16-byte vector shared load (LDS.128)
__device__ __forceinline__ ulonglong2 lds128(unsigned addr) {
    ulonglong2 v;
    asm("ld.shared.v2.u64 {%0, %1}, [%2];" : "=l"(v.x), "=l"(v.y) : "r"(addr));
    return v;
}

// ---------------- device scratch (allocation-free) ----------------
__device__ ull   g_Linv2[NS * LROW];     // padded-triangular T^-1, duplicated float2 (pads = 0)
__device__ ull   g_dmu2[NS * 32];        // incremental mean deltas (8-state groups), duplicated
__device__ float g_ld[NS];               // logdet per state (= 2*sum cc_ii)
__device__ float g_log_trans[NS * NS];   // log(softmax(T)+1e-8)
__device__ float g_log_init[NS];         // log softmax of initial distribution
__device__ int   g_rowargmax[NS];        // argmax of each transition row
__device__ float g_emlp[NROWS * NS];     // emission log probs, [b*L+t][s]

// =====================================================================
// Kernel 0: prep.
// Blocks 0..31 (warp 0 only): state s. chol(T T^t + eps I) ~= T, so we skip
// the Cholesky entirely: Linv = T^-1 by forward substitution (smem broadcast),
// logdet = 2*sum(cc_ii) exactly. Also writes the dmu table entry for s.
// Block 32 (32 warps): warp w handles transition row w; warp 0 also init dist.
// =====================================================================
__global__ void __launch_bounds__(1024) prep_kernel(const float* __restrict__ cc,
                                                    const float* __restrict__ means,
                                                    const float* __restrict__ tm,
                                                    const float* __restrict__ idist) {
    const int s    = blockIdx.x;
    const int tid  = threadIdx.x;
    const int lane = tid & 31;

    if (s < NS) {
        if (tid >= 32) return;
        __shared__ float T[32][33];

        // T = tril(cc[s]) with exp on diagonal
        #pragma unroll
        for (int i = 0; i < 32; i++) {
            float v = cc[s * 1024 + i * 32 + lane];
            if (lane > i) v = 0.0f;
            else if (lane == i) v = expf(v);
            T[i][lane] = v;
        }

        // logdet = 2 * sum(cc_ii)  (log(exp(cc_ii)) = cc_ii exactly)
        float dsum = cc[s * 1024 + lane * 33];
        #pragma unroll
        for (int o = 16; o; o >>= 1) dsum += __shfl_xor_sync(FULLMASK, dsum, o);
        if (lane == 0) g_ld[s] = 2.0f * dsum;
        __syncwarp();

        // Forward substitution: lane owns column `lane` of T^-1.
        // x[i] = (delta_{i,lane} - sum_{k<i} T[i][k]*x[k]) / T[i][i];  x[i]=0 for i<lane.
        float x[32];
        #pragma unroll
        for (int i = 0; i < 32; i++) {
            float se = (lane == i) ? 1.0f : 0.0f;
            float so = 0.0f;
            #pragma unroll
            for (int k = 0; k < i; k += 2) se -= T[i][k] * x[k];
            #pragma unroll
            for (int k = 1; k < i; k += 2) so -= T[i][k] * x[k];
            float ss = se + so;
            x[i] = (lane <= i) ? (ss / T[i][i]) : 0.0f;
        }

        // Store padded-triangular duplicated Linv. Row i starts at
        // R_i = tri(i) + ceil(i/2); even-i rows get a zero pad at R_i+i+1.
        #pragma unroll
        for (int i = 0; i < 32; i++) {
            const int Ri = i * (i + 1) / 2 + ((i + 1) >> 1);
            if (lane <= i)
                g_Linv2[s * LROW + Ri + lane] = pack2(x[i], x[i]);
            if (((i & 1) == 0) && lane == i + 1)
                g_Linv2[s * LROW + Ri + i + 1] = 0ull;
        }

        // dmu entry for this state (8-state groups for the emlp split):
        //   s%8==0: -mu[s]   else: mu[s-1]-mu[s]
        float dv = (s % 8 == 0) ? (-means[s * 32 + lane])
                                : (means[(s - 1) * 32 + lane] - means[s * 32 + lane]);
        g_dmu2[s * 32 + lane] = pack2(dv, dv);
    } else {
        // ---- transition prep: warp w = row w
        const int w = tid >> 5;

        float tv = tm[w * 32 + lane];
        float m2 = tv;
        #pragma unroll
        for (int o = 16; o; o >>= 1) m2 = fmaxf(m2, __shfl_xor_sync(FULLMASK, m2, o));
        float ee = expf(tv - m2);
        float ssum = ee;
        #pragma unroll
        for (int o = 16; o; o >>= 1) ssum += __shfl_xor_sync(FULLMASK, ssum, o);
        g_log_trans[w * 32 + lane] = logf(ee / ssum + 1e-8f);

        // first-occurrence argmax of the row (softmax is monotone)
        float bv = tv; int bi = lane;
        #pragma unroll
        for (int o = 16; o; o >>= 1) {
            float ov = __shfl_xor_sync(FULLMASK, bv, o);
            int   oi = __shfl_xor_sync(FULLMASK, bi, o);
            if (ov > bv || (ov == bv && oi < bi)) { bv = ov; bi = oi; }
        }
        if (lane == 0) g_rowargmax[w] = bi;

        if (w == 0) {
            float v = idist[lane];
            float mx = v;
            #pragma unroll
            for (int o = 16; o; o >>= 1) mx = fmaxf(mx, __shfl_xor_sync(FULLMASK, mx, o));
            float e = expf(v - mx);
            float sm = e;
            #pragma unroll
            for (int o = 16; o; o >>= 1) sm += __shfl_xor_sync(FULLMASK, sm, o);
            g_log_init[lane] = (v - mx) - logf(sm);
        }
    }
}

// =====================================================================
// Kernel 1: emission log probs.
// 2 rows per thread (one f32x2 pair); 8 states per block (blockIdx.y quarter).
// smem ~37KB, <=128 regs -> 4 blocks/SM = 16 warps/SM (2x latency hiding).
// L fetched via LDS.128 (2 duplicated elements per load).
// =====================================================================
__global__ void __launch_bounds__(128, 4) emlp_kernel(const float* __restrict__ em) {
    extern __shared__ ull sh[];
    // layout: [0, 4352) L (8 states * 544), [4352, 4608) dmu, then 8 floats logdet
    const int q = blockIdx.y;                 // state quarter 0..3
    const ull* gL = g_Linv2 + q * 8 * LROW;
    for (int i = threadIdx.x; i < 8 * LROW; i += 128) sh[i] = gL[i];
    const ull* gD = g_dmu2 + q * 256;
    for (int i = threadIdx.x; i < 256; i += 128) sh[4352 + i] = gD[i];
    float* sLd = (float*)(sh + 4608);
    if (threadIdx.x < 8) sLd[threadIdx.x] = g_ld[q * 8 + threadIdx.x];
    __syncthreads();

    const unsigned sbase = (unsigned)__cvta_generic_to_shared(sh);
    const unsigned dbase = sbase + 4352u * 8u;

    const int row0 = (blockIdx.x * 128 + threadIdx.x) * 2;
    const float4* p = (const float4*)(em + (size_t)row0 * 32);

    ull xa[32];   // (row0, row0+1) channel pairs
    #pragma unroll
    for (int qq = 0; qq < 8; qq++) {
        float4 f0 = p[qq], f1 = p[8 + qq];
        xa[4*qq+0] = pack2(f0.x, f1.x);
        xa[4*qq+1] = pack2(f0.y, f1.y);
        xa[4*qq+2] = pack2(f0.z, f1.z);
        xa[4*qq+3] = pack2(f0.w, f1.w);
    }

    float* outp = g_emlp + (size_t)row0 * NS + q * 8;

    for (int k = 0; k < 8; k++) {
        // xa += dmu_k  (16 LDS.128 serve 32 add2)
        const unsigned da = dbase + (unsigned)(k * 256);
        #pragma unroll
        for (int jp = 0; jp < 16; jp++) {
            ulonglong2 v = lds128(da + jp * 16);
            xa[2*jp]   = add2(xa[2*jp],   v.x);
            xa[2*jp+1] = add2(xa[2*jp+1], v.y);
        }

        const unsigned la = sbase + (unsigned)(k * LROW * 8);
        ull ma = 0ull;
        #pragma unroll
        for (int i = 0; i < 32; i++) {
            const int Ri = i * (i + 1) / 2 + ((i + 1) >> 1);
            const int np = (i + 2) >> 1;
            ull aA = 0ull, bA = 0ull;
            #pragma unroll
            for (int jp = 0; jp < np; jp++) {
                ulonglong2 v = lds128(la + (unsigned)((Ri + 2 * jp) * 8));
                aA = fma2(v.x, xa[2*jp],   aA);
                bA = fma2(v.y, xa[2*jp+1], bA);   // pad elems are 0 -> safe
            }
            ull sA = add2(aA, bA);
            ma = fma2(sA, sA, ma);               // mahal += solved^2 (both rows)
        }
        float2 m = unpack2(ma);
        const float c = sLd[k] + C_LOG2PI;
        outp[k]      = -0.5f * (m.x + c);
        outp[NS + k] = -0.5f * (m.y + c);
    }
}

// =====================================================================
// Kernel 2: fused Viterbi + AR prediction. One block (256 thr) per batch.
// =====================================================================
__global__ void __launch_bounds__(256) vp_kernel(const float* __restrict__ em,
                                                 const float* __restrict__ W,
                                                 const float* __restrict__ means,
                                                 float* __restrict__ out) {
    const int b    = blockIdx.x;
    const int lane = threadIdx.x & 31;
    const int g    = threadIdx.x >> 5;

    __shared__ float red[8][32];
    __shared__ int   s_state;

    // ---- AR partial sums (all 8 warps) ----
    const float* ebm = em + (size_t)b * NL * NC;
    float acc = 0.0f;
    #pragma unroll
    for (int l = 0; l < 32; l++) {
        const int ll = g * 32 + l;
        acc += ebm[ll * NC + lane] * W[ll * NC + lane];
    }
    red[g][lane] = acc;

    // ---- Viterbi (warp 0 only) ----
    if (g == 0) {
        float ltcol[32];
        #pragma unroll
        for (int i = 0; i < 32; i++) ltcol[i] = g_log_trans[i * 32 + lane];

        const float* eb = g_emlp + (size_t)b * NL * NS;
        float delta = g_log_init[lane] + eb[lane];

        #pragma unroll 4
        for (int t = 1; t < NL; t++) {
            const float emv = eb[t * NS + lane];
            float v[32];
            #pragma unroll
            for (int i = 0; i < 32; i++)
                v[i] = __shfl_sync(FULLMASK, delta, i) + ltcol[i];
            #pragma unroll
            for (int st = 16; st >= 1; st >>= 1) {
                #pragma unroll
                for (int i = 0; i < 16; i++)
                    if (i < st) v[i] = fmaxf(v[i], v[i + st]);
            }
            delta = v[0] + emv;
        }

        // first-occurrence argmax over lanes
        float bv = delta; int bi = lane;
        #pragma unroll
        for (int o = 16; o; o >>= 1) {
            float ov = __shfl_xor_sync(FULLMASK, bv, o);
            int   oi = __shfl_xor_sync(FULLMASK, bi, o);
            if (ov > bv || (ov == bv && oi < bi)) { bv = ov; bi = oi; }
        }
        if (lane == 0) s_state = g_rowargmax[bi];
    }
    __syncthreads();

    // ---- final combine (warp 0) ----
    if (g == 0) {
        float ssum = 0.0f;
        #pragma unroll
        for (int k = 0; k < 8; k++) ssum += red[k][lane];
        out[b * NC + lane] = ssum + means[s_state * NC + lane];
    }
}

// =====================================================================
extern "C" void kernel_launch(void* const* d_in, const int* in_sizes, int n_in,
                              void* d_out, int out_size) {
    const float* em    = (const float*)d_in[0];  // emissions (B,L,C)
    const float* tm    = (const float*)d_in[1];  // transition_matrix (S,S)
    const float* idist = (const float*)d_in[2];  // initial_distribution (S,)
    const float* means = (const float*)d_in[3];  // means (S,C)
    const float* cc    = (const float*)d_in[4];  // covar_chol (S,C,C)
    const float* W     = (const float*)d_in[5];  // W (LB,C,PW)
    float* out = (float*)d_out;

    prep_kernel<<<NS + 1, 1024>>>(cc, means, tm, idist);

    const int shbytes = 4608 * (int)sizeof(ull) + 8 * (int)sizeof(float);
    emlp_kernel<<<dim3(NROWS / 256, 4), 128, shbytes>>>(em);

    vp_kernel<<<NB, 256>>>(em, W, means, out);
}